// round 5
// baseline (speedup 1.0000x reference)
#include <cuda_runtime.h>
#include <cstdint>

// Problem constants
#define PB 8
#define PN 8192
#define PM 2048
#define PC 64
#define PS 32
#define OUTC 67              // 3 + 64
#define R2 1.0f

// Scratch (allocation-free rule: __device__ globals)
__device__ float  g_featT[PB * PN * PC];        // 16 MB, [b][n][c]
__device__ float4 g_xyz4[PB * PN];              // 1 MB, (x,y,z,p2)

// ---------------------------------------------------------------------------
// Kernel A: fused pack (xyz->float4+p2) + transpose (B,C,N)->(B,N,C)
// blocks 0..1023: transpose tiles (32c x 128n, float4 loads)
// blocks 1024..1279: pack
// ---------------------------------------------------------------------------
__global__ __launch_bounds__(256) void pre_kernel(
    const float* __restrict__ xyz, const float* __restrict__ f)
{
    const int bid = blockIdx.x;
    const int tx = threadIdx.x & 31;
    const int ty = threadIdx.x >> 5;      // 0..7

    if (bid < 1024) {
        __shared__ float4 tile[32][33];   // rows 528B, float4 writes conflict-free
        const int b   = bid >> 7;                 // /128
        const int rem = bid & 127;
        const int c0  = (rem >> 6) << 5;          // 0 or 32
        const int n0  = (rem & 63) << 7;          // 0..8064 step 128

#pragma unroll
        for (int k = 0; k < 4; ++k) {
            const int c = ty + (k << 3);          // 0..31
            const float4* src =
                (const float4*)(f + ((size_t)b * PC + c0 + c) * PN + n0);
            tile[c][tx] = src[tx];
        }
        __syncthreads();

        const float* tf = (const float*)&tile[tx][0];   // row of 132 floats (c=tx)
#pragma unroll
        for (int i = 0; i < 16; ++i) {
            const int n = (i << 3) + ty;          // 0..127
            g_featT[((size_t)b * PN + n0 + n) * PC + c0 + tx] = tf[n];
        }
    } else {
        const int i = (bid - 1024) * 256 + threadIdx.x;   // 0 .. B*N-1
        const float x = xyz[i * 3 + 0];
        const float y = xyz[i * 3 + 1];
        const float z = xyz[i * 3 + 2];
        const float p2 = __fadd_rn(__fadd_rn(__fmul_rn(x, x), __fmul_rn(y, y)),
                                   __fmul_rn(z, z));
        g_xyz4[i] = make_float4(x, y, z, p2);
    }
}

// ---------------------------------------------------------------------------
// Kernel B: FUSED ball query + group — one warp per query
//   Phase A: ascending scan, 128 pts/iter, early exit -> 32 neighbor idx
//   Phase B: cooperative smem-staged coalesced feature gather
//   Phase C: coalesced per-channel 128B stores
// ---------------------------------------------------------------------------
__global__ __launch_bounds__(128) void query_group_kernel(
    const float* __restrict__ new_xyz, float* __restrict__ out)
{
    __shared__ float sf[4][32 * 65];             // 33,280 B
    __shared__ int   slots[4][PS];

    const int w    = threadIdx.x >> 5;           // warp in block, 0..3
    const int lane = threadIdx.x & 31;
    const int q    = blockIdx.x * 4 + w;         // global query, 0..16383
    const int b    = q >> 11;
    const int m    = q & (PM - 1);

    // ---- Phase A: ball query ----
    const float* qp = new_xyz + (size_t)q * 3;
    const float qx = qp[0], qy = qp[1], qz = qp[2];
    const float q2 = __fadd_rn(__fadd_rn(__fmul_rn(qx, qx), __fmul_rn(qy, qy)),
                               __fmul_rn(qz, qz));

    int* slot = slots[w];
    const float4* base4 = g_xyz4 + (size_t)b * PN;
    int cnt = 0;
    for (int n0 = 0; n0 < PN && cnt < PS; n0 += 128) {
        const float4 c0 = base4[n0 +  0 + lane];
        const float4 c1 = base4[n0 + 32 + lane];
        const float4 c2 = base4[n0 + 64 + lane];
        const float4 c3 = base4[n0 + 96 + lane];

        float4 cs[4] = {c0, c1, c2, c3};
#pragma unroll
        for (int k = 0; k < 4; ++k) {
            const float4 p = cs[k];
            const float qd = __fadd_rn(__fadd_rn(__fmul_rn(qx, p.x), __fmul_rn(qy, p.y)),
                                       __fmul_rn(qz, p.z));
            const float d2 = __fadd_rn(__fadd_rn(q2, p.w), -__fmul_rn(2.0f, qd));
            const bool valid = d2 < R2;
            const unsigned bal = __ballot_sync(0xffffffffu, valid);
            if (valid) {
                const int pos = cnt + __popc(bal & ((1u << lane) - 1u));
                if (pos < PS) slot[pos] = n0 + (k << 5) + lane;
            }
            cnt += __popc(bal);
        }
    }
    __syncwarp();
    const int c = cnt < PS ? cnt : PS;           // >=1 (self point, dist 0)
    const int n_reg = (lane < c) ? slot[lane] : slot[0];
    __syncwarp();

    // ---- Phase B: cooperative gather into smem (coalesced featT reads) ----
    const float* fb = g_featT + (size_t)b * PN * PC;
    float* srowbase = sf[w];

#pragma unroll 8
    for (int j = 0; j < 32; ++j) {
        const int n = __shfl_sync(0xffffffffu, n_reg, j);
        const float* src = fb + (size_t)n * PC;
        const float a0 = src[lane];
        const float a1 = src[32 + lane];
        float* dst = srowbase + j * 65;
        dst[lane]      = a0;
        dst[32 + lane] = a1;
    }
    __syncwarp();

    // ---- Phase C: stores (lane = sample slot) ----
    const float4 p = g_xyz4[(size_t)b * PN + n_reg];

    const size_t chStride = (size_t)PM * PS;     // 65536
    const size_t basep = (size_t)b * OUTC * chStride + (size_t)m * PS + lane;

    out[basep + 0 * chStride] = p.x - qx;
    out[basep + 1 * chStride] = p.y - qy;
    out[basep + 2 * chStride] = p.z - qz;

    const float* srow = srowbase + lane * 65;
    float* o = out + basep + 3 * chStride;
#pragma unroll
    for (int ch = 0; ch < PC; ++ch)
        o[(size_t)ch * chStride] = srow[ch];
}

// ---------------------------------------------------------------------------
extern "C" void kernel_launch(void* const* d_in, const int* in_sizes, int n_in,
                              void* d_out, int out_size)
{
    const float* xyz   = nullptr;
    const float* nxyz  = nullptr;
    const float* feats = nullptr;
    for (int i = 0; i < n_in; ++i) {
        if      (in_sizes[i] == PB * PN * 3) xyz   = (const float*)d_in[i];
        else if (in_sizes[i] == PB * PM * 3) nxyz  = (const float*)d_in[i];
        else if (in_sizes[i] == PB * PC * PN) feats = (const float*)d_in[i];
    }
    float* out = (float*)d_out;
    (void)out_size;

    pre_kernel<<<1024 + 256, 256>>>(xyz, feats);          // pack + transpose
    query_group_kernel<<<(PB * PM) / 4, 128>>>(nxyz, out);
}

// round 6
// speedup vs baseline: 1.2983x; 1.2983x over previous
#include <cuda_runtime.h>
#include <cstdint>

// Problem constants
#define PB 8
#define PN 8192
#define PM 2048
#define PC 64
#define PS 32
#define OUTC 67              // 3 + 64
#define R2 1.0f

// Scratch (allocation-free rule: __device__ globals)
__device__ int    g_idx[PB * PM * PS];          // 2 MB
__device__ float  g_featT[PB * PN * PC];        // 16 MB, [b][n][c]
__device__ float4 g_xyz4[PB * PN];              // 1 MB, (x,y,z,p2)

// ---------------------------------------------------------------------------
// Kernel 0: pack xyz -> float4 with precomputed p2 (reference rounding)
// ---------------------------------------------------------------------------
__global__ __launch_bounds__(256) void pack_kernel(const float* __restrict__ xyz)
{
    const int i = blockIdx.x * blockDim.x + threadIdx.x;   // 0 .. B*N-1
    if (i >= PB * PN) return;
    const float x = xyz[i * 3 + 0];
    const float y = xyz[i * 3 + 1];
    const float z = xyz[i * 3 + 2];
    const float p2 = __fadd_rn(__fadd_rn(__fmul_rn(x, x), __fmul_rn(y, y)),
                               __fmul_rn(z, z));
    g_xyz4[i] = make_float4(x, y, z, p2);
}

// ---------------------------------------------------------------------------
// Kernel 1: transpose (DRAM-bound) + ball query (latency-bound) fused by
// blockIdx — independent inputs, complementary bottlenecks.
// blocks 0..1023   : transpose tiles (32c x 128n, float4 loads)
// blocks 1024..3071: ball query, 8 warps/block, 1 query/warp, 256 pts/iter
// ---------------------------------------------------------------------------
__global__ __launch_bounds__(256) void mid_kernel(
    const float* __restrict__ f, const float* __restrict__ new_xyz)
{
    __shared__ union {
        float4 tile[32][33];      // 16,896 B (transpose path)
        int    slots[8][PS];      //  1,024 B (query path)
    } sm;

    const int bid  = blockIdx.x;
    const int tx   = threadIdx.x & 31;
    const int ty   = threadIdx.x >> 5;     // 0..7

    if (bid < 1024) {
        // ---- transpose path ----
        const int b   = bid >> 7;                 // /128
        const int rem = bid & 127;
        const int c0  = (rem >> 6) << 5;          // 0 or 32
        const int n0  = (rem & 63) << 7;          // 0..8064 step 128

#pragma unroll
        for (int k = 0; k < 4; ++k) {
            const int c = ty + (k << 3);          // 0..31
            const float4* src =
                (const float4*)(f + ((size_t)b * PC + c0 + c) * PN + n0);
            sm.tile[c][tx] = src[tx];
        }
        __syncthreads();

        const float* tf = (const float*)&sm.tile[tx][0];  // 132 floats (c=tx)
#pragma unroll
        for (int i = 0; i < 16; ++i) {
            const int n = (i << 3) + ty;          // 0..127
            g_featT[((size_t)b * PN + n0 + n) * PC + c0 + tx] = tf[n];
        }
    } else {
        // ---- ball query path ----
        const int wid  = (bid - 1024) * 8 + ty;   // global query 0..16383
        const int lane = tx;
        const int b = wid >> 11;
        const int m = wid & (PM - 1);

        const float* q = new_xyz + ((size_t)b * PM + m) * 3;
        const float qx = q[0], qy = q[1], qz = q[2];
        const float q2 = __fadd_rn(__fadd_rn(__fmul_rn(qx, qx), __fmul_rn(qy, qy)),
                                   __fmul_rn(qz, qz));

        int* slot = sm.slots[ty];
        const float4* base4 = g_xyz4 + (size_t)b * PN;
        int cnt = 0;
        for (int n0 = 0; n0 < PN && cnt < PS; n0 += 256) {
            float4 cs[8];
#pragma unroll
            for (int k = 0; k < 8; ++k)
                cs[k] = base4[n0 + (k << 5) + lane];
#pragma unroll
            for (int k = 0; k < 8; ++k) {
                const float4 p = cs[k];
                const float qd = __fadd_rn(__fadd_rn(__fmul_rn(qx, p.x), __fmul_rn(qy, p.y)),
                                           __fmul_rn(qz, p.z));
                const float d2 = __fadd_rn(__fadd_rn(q2, p.w), -__fmul_rn(2.0f, qd));
                const bool valid = d2 < R2;
                const unsigned bal = __ballot_sync(0xffffffffu, valid);
                if (valid) {
                    const int pos = cnt + __popc(bal & ((1u << lane) - 1u));
                    if (pos < PS) slot[pos] = n0 + (k << 5) + lane;
                }
                cnt += __popc(bal);
            }
        }
        __syncwarp();
        const int c = cnt < PS ? cnt : PS;        // >=1 (self point, dist 0)
        const int first = slot[0];
        const int v = (lane < c) ? slot[lane] : first;
        g_idx[(size_t)wid * PS + lane] = v;
    }
}

// ---------------------------------------------------------------------------
// Kernel 2: group — warp per query, smem-staged coalesced gather (R2 version)
// ---------------------------------------------------------------------------
__global__ __launch_bounds__(128) void group_kernel(
    const float* __restrict__ new_xyz, float* __restrict__ out)
{
    __shared__ float sf[128 * 65];               // 33,280 B
    const int w    = threadIdx.x >> 5;           // warp in block, 0..3
    const int lane = threadIdx.x & 31;
    const int q    = blockIdx.x * 4 + w;         // global query, 0..16383
    const int b    = q >> 11;
    const int m    = q & (PM - 1);

    // lane j holds neighbor index of sample j
    const int n_reg = g_idx[(size_t)q * PS + lane];

    const float* fb = g_featT + (size_t)b * PN * PC;
    float* srowbase = sf + (size_t)(w * 32) * 65;

#pragma unroll 8
    for (int j = 0; j < 32; ++j) {
        const int n = __shfl_sync(0xffffffffu, n_reg, j);
        const float* src = fb + (size_t)n * PC;
        const float a0 = src[lane];
        const float a1 = src[32 + lane];
        float* dst = srowbase + j * 65;
        dst[lane]      = a0;
        dst[32 + lane] = a1;
    }
    __syncwarp();

    // Phase 2: lane = sample slot s
    const float* qp = new_xyz + (size_t)q * 3;
    const float qx = qp[0], qy = qp[1], qz = qp[2];
    const float4 p = g_xyz4[(size_t)b * PN + n_reg];

    const size_t chStride = (size_t)PM * PS;     // 65536
    const size_t basep = (size_t)b * OUTC * chStride + (size_t)m * PS + lane;

    out[basep + 0 * chStride] = p.x - qx;
    out[basep + 1 * chStride] = p.y - qy;
    out[basep + 2 * chStride] = p.z - qz;

    const float* srow = srowbase + lane * 65;
    float* o = out + basep + 3 * chStride;
#pragma unroll
    for (int c = 0; c < PC; ++c)
        o[(size_t)c * chStride] = srow[c];
}

// ---------------------------------------------------------------------------
extern "C" void kernel_launch(void* const* d_in, const int* in_sizes, int n_in,
                              void* d_out, int out_size)
{
    const float* xyz   = nullptr;
    const float* nxyz  = nullptr;
    const float* feats = nullptr;
    for (int i = 0; i < n_in; ++i) {
        if      (in_sizes[i] == PB * PN * 3) xyz   = (const float*)d_in[i];
        else if (in_sizes[i] == PB * PM * 3) nxyz  = (const float*)d_in[i];
        else if (in_sizes[i] == PB * PC * PN) feats = (const float*)d_in[i];
    }
    float* out = (float*)d_out;
    (void)out_size;

    pack_kernel<<<(PB * PN + 255) / 256, 256>>>(xyz);
    mid_kernel<<<1024 + 2048, 256>>>(feats, nxyz);        // transpose ∥ ball query
    group_kernel<<<(PB * PM) / 4, 128>>>(nxyz, out);
}